// round 2
// baseline (speedup 1.0000x reference)
#include <cuda_runtime.h>

// MultiScaleRoIAlign: 4-level FPN, RoIAlign(aligned=False), OUT=7, SR=2.
// feats: [2,256,200,200],[2,256,100,100],[2,256,50,50],[2,256,25,25] fp32
// boxes: [2,256,4] fp32 -> out: [512,256,7,7] fp32
//
// Mapping: one block per RoI (512 blocks), one thread per channel (256).
// Per-RoI separable sample tables (14 y-taps, 14 x-taps) built once in smem.

#define NLVL 4

__global__ __launch_bounds__(256) void roi_align_kernel(
    const float* __restrict__ f0, const float* __restrict__ f1,
    const float* __restrict__ f2, const float* __restrict__ f3,
    const float* __restrict__ boxes, float* __restrict__ out)
{
    const int r = blockIdx.x;      // roi index 0..511
    const int c = threadIdx.x;     // channel 0..255
    const int b = r >> 8;          // batch = r / 256

    // ---- per-RoI scalars (computed redundantly per thread; cheap) ----
    const float bx1 = boxes[r * 4 + 0];
    const float by1 = boxes[r * 4 + 1];
    const float bx2 = boxes[r * 4 + 2];
    const float by2 = boxes[r * 4 + 3];

    // level mapper: clip(floor(4 + log2(sqrt(area)/224 + 1e-6)), 2, 5) - 2
    const float area = (bx2 - bx1) * (by2 - by1);
    const float ssz  = sqrtf(area);
    float lv = floorf(4.0f + log2f(ssz / 224.0f + 1e-6f));
    lv = fminf(fmaxf(lv, 2.0f), 5.0f);
    const int level = (int)lv - 2;

    const int   Htab[NLVL]  = {200, 100, 50, 25};
    const float sctab[NLVL] = {0.25f, 0.125f, 0.0625f, 0.03125f};
    const int   H  = Htab[level];
    const int   W  = H;
    const float sc = sctab[level];
    const float* feat = (level == 0) ? f0 : (level == 1) ? f1 : (level == 2) ? f2 : f3;

    const float x1 = bx1 * sc, y1 = by1 * sc;
    const float x2 = bx2 * sc, y2 = by2 * sc;
    const float roi_w = fmaxf(x2 - x1, 1.0f);
    const float roi_h = fmaxf(y2 - y1, 1.0f);
    const float bin_w = roi_w / 7.0f;
    const float bin_h = roi_h / 7.0f;

    // ---- separable sample tables: 14 y entries, 14 x entries ----
    __shared__ int   s_ylW[14], s_yhW[14];   // row offsets (yl*W, yh*W)
    __shared__ int   s_xl[14],  s_xh[14];
    __shared__ float s_ly[14],  s_lx[14];    // fractional parts
    __shared__ float s_vy[14],  s_vx[14];    // validity masks (0/1)

    if (c < 30) {
        const bool isx = (c >= 16);          // lanes 0..13 -> y, 16..29 -> x
        const int  jj  = isx ? (c - 16) : c;
        if (jj < 14) {
            const int ph = jj >> 1;
            const int ii = jj & 1;
            const float g   = (float)ph + ((float)ii + 0.5f) * 0.5f;   // ph + (i+0.5)/SR
            float pos = isx ? (x1 + g * bin_w) : (y1 + g * bin_h);
            const float lim = (float)H;                                // square: W==H
            const float vld = (pos >= -1.0f && pos <= lim) ? 1.0f : 0.0f;
            pos = fmaxf(pos, 0.0f);
            int lo = (int)pos;                 // trunc == floor for pos>=0
            int hi;
            if (lo >= H - 1) { lo = H - 1; hi = H - 1; pos = (float)lo; }
            else             { hi = lo + 1; }
            const float frac = pos - (float)lo;
            if (isx) { s_xl[jj] = lo;       s_xh[jj] = hi;       s_lx[jj] = frac; s_vx[jj] = vld; }
            else     { s_ylW[jj] = lo * W;  s_yhW[jj] = hi * W;  s_ly[jj] = frac; s_vy[jj] = vld; }
        }
    }
    __syncthreads();

    // ---- hot loop: pure gather + FMA ----
    const float* fp = feat + (size_t)(b * 256 + c) * (size_t)(H * W);
    float* op = out + ((size_t)r * 256 + c) * 49;

    for (int ph = 0; ph < 7; ph++) {
        const int jy0 = 2 * ph;
        const float ly0 = s_ly[jy0],     hy0 = 1.0f - ly0, vy0 = s_vy[jy0];
        const float ly1 = s_ly[jy0 + 1], hy1 = 1.0f - ly1, vy1 = s_vy[jy0 + 1];
        const int ra0 = s_ylW[jy0],     rb0 = s_yhW[jy0];
        const int ra1 = s_ylW[jy0 + 1], rb1 = s_yhW[jy0 + 1];

        #pragma unroll
        for (int pw = 0; pw < 7; pw++) {
            const int jx0 = 2 * pw;
            float acc = 0.0f;
            #pragma unroll
            for (int ix = 0; ix < 2; ix++) {
                const int jx = jx0 + ix;
                const float lx = s_lx[jx], hx = 1.0f - lx, vx = s_vx[jx];
                const int xl = s_xl[jx], xh = s_xh[jx];

                // sample (iy=0)
                {
                    const float v00 = fp[ra0 + xl];
                    const float v01 = fp[ra0 + xh];
                    const float v10 = fp[rb0 + xl];
                    const float v11 = fp[rb0 + xh];
                    const float bil = hy0 * (hx * v00 + lx * v01)
                                    + ly0 * (hx * v10 + lx * v11);
                    acc += (vy0 * vx) * bil;
                }
                // sample (iy=1)
                {
                    const float v00 = fp[ra1 + xl];
                    const float v01 = fp[ra1 + xh];
                    const float v10 = fp[rb1 + xl];
                    const float v11 = fp[rb1 + xh];
                    const float bil = hy1 * (hx * v00 + lx * v01)
                                    + ly1 * (hx * v10 + lx * v11);
                    acc += (vy1 * vx) * bil;
                }
            }
            op[ph * 7 + pw] = acc * 0.25f;
        }
    }
}

extern "C" void kernel_launch(void* const* d_in, const int* in_sizes, int n_in,
                              void* d_out, int out_size) {
    const int nroi = in_sizes[4] / 4;   // 512
    roi_align_kernel<<<nroi, 256>>>(
        (const float*)d_in[0], (const float*)d_in[1],
        (const float*)d_in[2], (const float*)d_in[3],
        (const float*)d_in[4], (float*)d_out);
}

// round 3
// speedup vs baseline: 1.3318x; 1.3318x over previous
#include <cuda_runtime.h>

// MultiScaleRoIAlign: 4-level FPN, RoIAlign(aligned=False), OUT=7, SR=2.
// feats: [2,256,200,200],[2,256,100,100],[2,256,50,50],[2,256,25,25] fp32
// boxes: [2,256,4] fp32 -> out: [512,256,7,7] fp32
//
// One block per RoI. The RoI's sampled region (<= ~900 cells by the level
// mapper's size invariant) is staged into smem for 8 channels at a time with
// coalesced loads; the 7x7x(2x2 samples) bilinear pooling then runs entirely
// out of smem. This removes the 32-way lane divergence (1 sector per lane)
// that made round-2 L1-wavefront-bound.

#define NLVL 4
#define GRP 8
#define MAXCELLS 1024

__global__ __launch_bounds__(256) void roi_align_kernel(
    const float* __restrict__ f0, const float* __restrict__ f1,
    const float* __restrict__ f2, const float* __restrict__ f3,
    const float* __restrict__ boxes, float* __restrict__ out)
{
    const int r   = blockIdx.x;     // roi 0..511
    const int tid = threadIdx.x;    // 0..255
    const int b   = r >> 8;

    // ---- per-RoI geometry (redundant per thread) ----
    const float bx1 = boxes[r * 4 + 0];
    const float by1 = boxes[r * 4 + 1];
    const float bx2 = boxes[r * 4 + 2];
    const float by2 = boxes[r * 4 + 3];

    const float area = (bx2 - bx1) * (by2 - by1);
    float lv = floorf(4.0f + log2f(sqrtf(area) / 224.0f + 1e-6f));
    lv = fminf(fmaxf(lv, 2.0f), 5.0f);
    const int level = (int)lv - 2;

    const int   Htab[NLVL]  = {200, 100, 50, 25};
    const float sctab[NLVL] = {0.25f, 0.125f, 0.0625f, 0.03125f};
    const int   H  = Htab[level];
    const int   W  = H;
    const float sc = sctab[level];
    const float* feat = (level == 0) ? f0 : (level == 1) ? f1 : (level == 2) ? f2 : f3;

    const float x1 = bx1 * sc, y1 = by1 * sc;
    const float roi_w = fmaxf(bx2 * sc - x1, 1.0f);
    const float roi_h = fmaxf(by2 * sc - y1, 1.0f);
    const float bin_w = roi_w / 7.0f;
    const float bin_h = roi_h / 7.0f;

    // ---- sample tables (global indices) ----
    __shared__ int   s_yl[14], s_yh[14], s_xl[14], s_xh[14];
    __shared__ float s_ly[14], s_lx[14], s_vy[14], s_vx[14];
    // region-local derived tables
    __shared__ int   s_ra[14], s_rb[14], s_xll[14], s_xhl[14];
    __shared__ float s_reg[GRP * MAXCELLS];   // 32 KB

    if (tid < 30) {
        const bool isx = (tid >= 16);            // 0..13 -> y, 16..29 -> x
        const int  jj  = isx ? (tid - 16) : tid;
        if (jj < 14) {
            const int ph = jj >> 1;
            const int ii = jj & 1;
            const float g = (float)ph + ((float)ii + 0.5f) * 0.5f;  // ph + (i+0.5)/SR
            float pos = isx ? (x1 + g * bin_w) : (y1 + g * bin_h);
            const float lim = (float)H;                             // square
            const float vld = (pos >= -1.0f && pos <= lim) ? 1.0f : 0.0f;
            pos = fmaxf(pos, 0.0f);
            int lo = (int)pos;
            int hi;
            if (lo >= H - 1) { lo = H - 1; hi = H - 1; pos = (float)lo; }
            else             { hi = lo + 1; }
            const float frac = pos - (float)lo;
            if (isx) { s_xl[jj] = lo; s_xh[jj] = hi; s_lx[jj] = frac; s_vx[jj] = vld; }
            else     { s_yl[jj] = lo; s_yh[jj] = hi; s_ly[jj] = frac; s_vy[jj] = vld; }
        }
    }
    __syncthreads();

    // sample positions are monotone, so region bounds come from the table ends
    const int ry0 = s_yl[0], ry1 = s_yh[13];
    const int rx0 = s_xl[0], rx1 = s_xh[13];
    const int nrows = ry1 - ry0 + 1;
    const int ncols = rx1 - rx0 + 1;
    const int cells = nrows * ncols;

    if (cells <= MAXCELLS) {
        // ---- fast path: smem-staged region ----
        if (tid < 14) {
            s_ra[tid]  = (s_yl[tid] - ry0) * ncols;
            s_rb[tid]  = (s_yh[tid] - ry0) * ncols;
            s_xll[tid] = s_xl[tid] - rx0;
            s_xhl[tid] = s_xh[tid] - rx0;
        }
        __syncthreads();

        const size_t plane = (size_t)H * W;
        const float* fbase = feat + (size_t)b * 256 * plane;

        for (int c0 = 0; c0 < 256; c0 += GRP) {
            // stage GRP channel-regions, coalesced along x
            const int total = GRP * cells;
            for (int i = tid; i < total; i += 256) {
                const int g   = i / cells;
                const int rem = i - g * cells;
                const int row = rem / ncols;
                const int col = rem - row * ncols;
                s_reg[g * MAXCELLS + rem] =
                    fbase[(size_t)(c0 + g) * plane + (size_t)(ry0 + row) * W + (rx0 + col)];
            }
            __syncthreads();

            // compute GRP*49 outputs from smem
            for (int e = tid; e < GRP * 49; e += 256) {
                const int g   = e / 49;
                const int bin = e - g * 49;
                const int ph  = bin / 7;
                const int pw  = bin - ph * 7;
                const float* S = s_reg + g * MAXCELLS;

                float acc = 0.0f;
                #pragma unroll
                for (int iy = 0; iy < 2; iy++) {
                    const int jy = 2 * ph + iy;
                    const float ly = s_ly[jy], hy = 1.0f - ly, vy = s_vy[jy];
                    const int ra = s_ra[jy], rb = s_rb[jy];
                    #pragma unroll
                    for (int ix = 0; ix < 2; ix++) {
                        const int jx = 2 * pw + ix;
                        const float lx = s_lx[jx], hx = 1.0f - lx, vx = s_vx[jx];
                        const int xl = s_xll[jx], xh = s_xhl[jx];
                        const float bil = hy * (hx * S[ra + xl] + lx * S[ra + xh])
                                        + ly * (hx * S[rb + xl] + lx * S[rb + xh]);
                        acc += (vy * vx) * bil;
                    }
                }
                out[((size_t)r * 256 + (c0 + g)) * 49 + bin] = acc * 0.25f;
            }
            __syncthreads();
        }
    } else {
        // ---- fallback (unreachable for this data distribution, kept for safety):
        // direct gmem gather, one thread per channel ----
        const int c = tid;
        const float* fp = feat + (size_t)(b * 256 + c) * (size_t)H * W;
        float* op = out + ((size_t)r * 256 + c) * 49;

        for (int ph = 0; ph < 7; ph++) {
            #pragma unroll
            for (int pw = 0; pw < 7; pw++) {
                float acc = 0.0f;
                #pragma unroll
                for (int iy = 0; iy < 2; iy++) {
                    const int jy = 2 * ph + iy;
                    const float ly = s_ly[jy], hy = 1.0f - ly, vy = s_vy[jy];
                    const int ra = s_yl[jy] * W, rb = s_yh[jy] * W;
                    #pragma unroll
                    for (int ix = 0; ix < 2; ix++) {
                        const int jx = 2 * pw + ix;
                        const float lx = s_lx[jx], hx = 1.0f - lx, vx = s_vx[jx];
                        const int xl = s_xl[jx], xh = s_xh[jx];
                        const float bil = hy * (hx * fp[ra + xl] + lx * fp[ra + xh])
                                        + ly * (hx * fp[rb + xl] + lx * fp[rb + xh]);
                        acc += (vy * vx) * bil;
                    }
                }
                op[ph * 7 + pw] = acc * 0.25f;
            }
        }
    }
}

extern "C" void kernel_launch(void* const* d_in, const int* in_sizes, int n_in,
                              void* d_out, int out_size) {
    const int nroi = in_sizes[4] / 4;   // 512
    roi_align_kernel<<<nroi, 256>>>(
        (const float*)d_in[0], (const float*)d_in[1],
        (const float*)d_in[2], (const float*)d_in[3],
        (const float*)d_in[4], (float*)d_out);
}